// round 15
// baseline (speedup 1.0000x reference)
#include <cuda_runtime.h>
#include <stdint.h>

#define TPB 128
#define WPB 4
#define NVOX 1000000u
#define RSB 20u  // smem row stride in floats (80B): conflict-free phases

typedef unsigned long long u64;

// ---------------- packed f32x2 helpers (Blackwell) ----------------
__device__ __forceinline__ u64 pk2(float lo, float hi) {
    u64 r;
    asm("mov.b64 %0, {%1, %2};" : "=l"(r) : "f"(lo), "f"(hi));
    return r;
}
__device__ __forceinline__ void unpk2(u64 v, float &lo, float &hi) {
    asm("mov.b64 {%0, %1}, %2;" : "=f"(lo), "=f"(hi) : "l"(v));
}
__device__ __forceinline__ u64 fma2(u64 a, u64 b, u64 c) {
    u64 d;
    asm("fma.rn.f32x2 %0, %1, %2, %3;" : "=l"(d) : "l"(a), "l"(b), "l"(c));
    return d;
}

// add on the FMA pipe: d = a*one + b, `one` runtime-opaque (==1).
__device__ __forceinline__ uint32_t imadd(uint32_t a, uint32_t one,
                                          uint32_t b) {
    uint32_t r;
    asm("mad.lo.u32 %0, %1, %2, %3;" : "=r"(r) : "r"(a), "r"(one), "r"(b));
    return r;
}

// ---------------- cp.async 16B ----------------
__device__ __forceinline__ void cp_async16(uint32_t saddr, const void *gptr) {
    asm volatile("cp.async.ca.shared.global [%0], [%1], 16;"
                 :: "r"(saddr), "l"(gptr) : "memory");
}
__device__ __forceinline__ void cp_commit() {
    asm volatile("cp.async.commit_group;" ::: "memory");
}
__device__ __forceinline__ void cp_wait0() {
    asm volatile("cp.async.wait_group 0;" ::: "memory");
}

// ------- threefry2x32, key = jax.random.key(42) -> (k1=0, k2=42) ----------
__device__ __forceinline__ uint32_t tf_bits_partitionable(uint32_t i,
                                                          uint32_t one) {
    const uint32_t KS1 = 42u;
    const uint32_t KS2 = 0x1BD11BDAu ^ 42u;  // ks0=0
    uint32_t x0 = 0u;
    uint32_t x1 = imadd(i, one, KS1);
#define TF_R(r)                                   \
    {                                             \
        x0 = imadd(x0, one, x1);                  \
        x1 = __funnelshift_l(x1, x1, (r)) ^ x0;   \
    }
#define TF_G1 TF_R(13) TF_R(15) TF_R(26) TF_R(6)
#define TF_G2 TF_R(17) TF_R(29) TF_R(16) TF_R(24)
    TF_G1 x0 = imadd(x0, one, KS1); x1 = imadd(x1, one, KS2 + 1u);
    TF_G2 x0 = imadd(x0, one, KS2); x1 = imadd(x1, one, 2u);       // ks0+2
    TF_G1                           x1 = imadd(x1, one, KS1 + 3u); // x0+=0
    TF_G2 x0 = imadd(x0, one, KS1); x1 = imadd(x1, one, KS2 + 4u);
    TF_G1 x0 = imadd(x0, one, KS2); x1 = imadd(x1, one, 5u);       // ks0+5
#undef TF_G1
#undef TF_G2
#undef TF_R
    return x0 ^ x1;  // partitionable path: lane0 ^ lane1
}

// bits -> jax.random.normal sample * 1e-6 (SYMEIG_EPS); trimmed ErfInv32.
__device__ __forceinline__ float noise_from_bits(uint32_t bits,
                                                 uint32_t one) {
    const float LO = -0.99999994f;       // nextafter(-1,0)
    const float NLN2 = -0.6931471805599453f;
    float F = __uint_as_float(imadd(bits >> 9, one, 0x3f800000u));  // [1,2)
    float u = fmaxf(LO, fmaf(F, 2.0f, -3.0f));
    float z = 1.0f - u * u;              // Sterbenz-exact in the tail
    float L = __log2f(z);                // <= 0
    float ws = fmaf(L, NLN2, -2.5f);     // = w - 2.5
    float p1 = fmaf(2.81022636e-08f, ws, 3.43273939e-07f);
    p1 = fmaf(p1, ws, -3.5233877e-06f);
    p1 = fmaf(p1, ws, -4.39150654e-06f);
    p1 = fmaf(p1, ws, 0.00021858087f);
    p1 = fmaf(p1, ws, -0.00125372503f);
    p1 = fmaf(p1, ws, -0.00417768164f);
    p1 = fmaf(p1, ws, 0.246640727f);
    p1 = fmaf(p1, ws, 1.50140941f);
    bool big = (L <= -7.2134752f);       // w >= 5
    if (__any_sync(0xffffffffu, big)) {
        float wb = __fsqrt_rn(NLN2 * L) - 3.0f;
        float p2 = fmaf(-0.000200214257f, wb, 0.000100950558f);
        p2 = fmaf(p2, wb, 0.00134934322f);
        p2 = fmaf(p2, wb, -0.00367342844f);
        p2 = fmaf(p2, wb, 0.00573950773f);
        p2 = fmaf(p2, wb, -0.0076224613f);
        p2 = fmaf(p2, wb, 0.00943887047f);
        p2 = fmaf(p2, wb, 1.00167406f);
        p2 = fmaf(p2, wb, 2.83297682f);
        p1 = big ? p2 : p1;
    }
    return 1.4142135452078743e-06f * (p1 * u);  // 1e-6 * sqrt2 folded
}

// --------- FA from symmetric 3x3 (noise pre-reduced to 6 values) ----------
__device__ __forceinline__ float fa_voxel(float f0, float f1, float f2,
                                          float f3, float f4, float f5,
                                          float n00, float n11, float n22,
                                          float h01, float h02, float h12,
                                          float mind) {
    float a00 = f0 + n00;
    float a11 = f2 + n11;
    float a22 = f5 + n22;
    float a01 = f1 + h01;
    float a02 = f3 + h02;
    float a12 = f4 + h12;

    float q = (a00 + a11 + a22) * (1.0f / 3.0f);
    float m0 = a00 - q, m1 = a11 - q, m2 = a22 - q;
    float off = fmaf(a01, a01, fmaf(a02, a02, a12 * a12));
    float S = fmaf(m0, m0, fmaf(m1, m1, fmaf(m2, m2, 2.0f * off)));
    float fa_fast = __fsqrt_rn(__fdividef(1.5f * S, fmaf(3.0f * q, q, S)));
    float p = __fsqrt_rn(S * (1.0f / 6.0f));
    if (q - 2.0f * p >= mind) return fa_fast;  // lambda_min >= q-2p always

    float det = m0 * fmaf(m1, m2, -a12 * a12)
              - a01 * fmaf(a01, m2, -a12 * a02)
              + a02 * fmaf(a01, a12, -m1 * a02);
    float pinv = __fdividef(1.0f, p);
    float r = 0.5f * det * pinv * pinv * pinv;
    r = fminf(fmaxf(r, -1.0f), 1.0f);  // NaN (p==0) collapses to -1
    float phi = acosf(r) * (1.0f / 3.0f);
    float l3 = fmaf(2.0f * p, __cosf(phi + 2.0943951023931953f), q);  // min
    if (l3 >= mind) return fa_fast;

    float l1 = fmaf(2.0f * p, __cosf(phi), q);  // max
    float l2 = 3.0f * q - l1 - l3;
    l1 = fmaxf(l1, mind);
    l2 = fmaxf(l2, mind);
    l3 = fmaxf(l3, mind);
    float d12 = l1 - l2, d23 = l2 - l3, d31 = l3 - l1;
    float num = 0.5f * fmaf(d12, d12, fmaf(d23, d23, d31 * d31));
    float den = fmaf(l1, l1, fmaf(l2, l2, l3 * l3));
    return __fsqrt_rn(__fdividef(num, den));
}

// load phase P (elems [16P,16P+16)) of 32 voxels starting at BASE into rows
// starting at byte R0 of this warp's tile. lane (g2=lane>>2, e2=lane&3)
// covers chunk e2 of voxels {g2, g2+8, g2+16, g2+24}. 128B-coalesced pairs.
#define LOADP(R0, BASE, P)                                                     \
    do {                                                                       \
        _Pragma("unroll") for (int _k = 0; _k < 4; ++_k)                       \
            cp_async16(trow_sa + (R0) +                                        \
                           (g2 + (unsigned)(_k * 8)) * (RSB * 4u) + e2 * 16u,  \
                       dwi4 + (size_t)((BASE) + (unsigned)(_k * 8) + g2) *     \
                                  16u + (unsigned)(4 * (P)) + e2);             \
        cp_commit();                                                           \
    } while (0)

// one jt step for BOTH voxels, sharing the 6 W loads
#define CONSUME2(JT, WOFF)                                                     \
    do {                                                                       \
        float4 _a = *reinterpret_cast<const float4 *>(&rowA[(JT) * 4]);        \
        float4 _b = *reinterpret_cast<const float4 *>(&rowB[(JT) * 4]);        \
        float _a0 = __log2f(fmaxf(_a.x, mind));                                \
        float _a1 = __log2f(fmaxf(_a.y, mind));                                \
        float _a2 = __log2f(fmaxf(_a.z, mind));                                \
        float _a3 = __log2f(fmaxf(_a.w, mind));                                \
        float _b0 = __log2f(fmaxf(_b.x, mind));                                \
        float _b1 = __log2f(fmaxf(_b.y, mind));                                \
        float _b2 = __log2f(fmaxf(_b.z, mind));                                \
        float _b3 = __log2f(fmaxf(_b.w, mind));                                \
        u64 _la01 = pk2(_a0, _a1), _la23 = pk2(_a2, _a3);                      \
        u64 _lb01 = pk2(_b0, _b1), _lb23 = pk2(_b2, _b3);                      \
        _Pragma("unroll") for (int _i = 0; _i < 6; ++_i) {                     \
            ulonglong2 _w = *reinterpret_cast<const ulonglong2 *>(             \
                &Wsh[_i * 64 + (WOFF) + (JT) * 4]);                            \
            accA[_i] = fma2(_w.x, _la01, accA[_i]);                            \
            accA[_i] = fma2(_w.y, _la23, accA[_i]);                            \
            accB[_i] = fma2(_w.x, _lb01, accB[_i]);                            \
            accB[_i] = fma2(_w.y, _lb23, accB[_i]);                            \
        }                                                                      \
    } while (0)

#define NS(base, j) noise_from_bits(tf_bits_partitionable((base) + (j), one), one)

// ---------------- main kernel ----------------------------------------------
__global__ void __launch_bounds__(TPB, 8)
fa_kernel(const float *__restrict__ dwi, const float *__restrict__ mask,
          const float *__restrict__ Winv, const float *__restrict__ mindp,
          float *__restrict__ out) {
    __shared__ __align__(16) float Wsh[384];
    __shared__ __align__(16) float tile[WPB][64 * RSB];

    for (int k = threadIdx.x; k < 384; k += TPB)
        Wsh[k] = Winv[k] * 0.6931471805599453f;
    __syncthreads();  // Wsh only; tile is warp-private

    const int warp = threadIdx.x >> 5;
    const int lane = threadIdx.x & 31;
    const unsigned vw = (blockIdx.x * WPB + warp) * 64u;  // 64 voxels/warp
    if (vw >= NVOX) return;  // NVOX % 64 == 0: surviving warps are FULL

    const unsigned vA = vw + (unsigned)lane;  // voxel A
    const unsigned vB = vA + 32u;             // voxel B

    const float mind = __ldg(mindp);
    const uint32_t one = (mind > 0.0f) ? 1u : 2u;  // runtime-opaque 1
    const float4 *__restrict__ dwi4 = reinterpret_cast<const float4 *>(dwi);
    float *trow = &tile[warp][0];
    const uint32_t trow_sa =
        (uint32_t)__cvta_generic_to_shared(&tile[warp][0]);
    const unsigned g2 = lane >> 2u, e2 = lane & 3u;
    const float *rowA = &trow[lane * RSB];
    const float *rowB = &trow[(32 + lane) * RSB];
    const uint32_t nbA = 9u * vA, nbB = 9u * vB;

    u64 accA[6], accB[6];
#pragma unroll
    for (int i = 0; i < 6; ++i) { accA[i] = 0ull; accB[i] = 0ull; }

    // ---- phase 0 loads + noise A0,A1 ----
    LOADP(0u, vw, 0);
    LOADP(32u * RSB * 4u, vw + 32u, 0);
    float nA00 = NS(nbA, 0u);
    float a1   = NS(nbA, 1u);

    cp_wait0();
    __syncwarp();
    CONSUME2(0, 0);
    CONSUME2(1, 0);
    float a2 = NS(nbA, 2u);
    CONSUME2(2, 0);
    CONSUME2(3, 0);
    __syncwarp();
    LOADP(0u, vw, 1);
    LOADP(32u * RSB * 4u, vw + 32u, 1);
    float a3 = NS(nbA, 3u);
    float hA01 = 0.5f * (a1 + a3);
    float nA11 = NS(nbA, 4u);

    cp_wait0();
    __syncwarp();
    CONSUME2(0, 16);
    CONSUME2(1, 16);
    float a5 = NS(nbA, 5u);
    CONSUME2(2, 16);
    CONSUME2(3, 16);
    __syncwarp();
    LOADP(0u, vw, 2);
    LOADP(32u * RSB * 4u, vw + 32u, 2);
    float a6 = NS(nbA, 6u);
    float hA02 = 0.5f * (a2 + a6);
    float a7 = NS(nbA, 7u);
    float hA12 = 0.5f * (a5 + a7);
    float nA22 = NS(nbA, 8u);

    cp_wait0();
    __syncwarp();
    CONSUME2(0, 32);
    CONSUME2(1, 32);
    float nB00 = NS(nbB, 0u);
    CONSUME2(2, 32);
    CONSUME2(3, 32);
    __syncwarp();
    LOADP(0u, vw, 3);
    LOADP(32u * RSB * 4u, vw + 32u, 3);
    const float mvA = __ldg(mask + vA);
    const float mvB = __ldg(mask + vB);
    float b1 = NS(nbB, 1u);
    float b2 = NS(nbB, 2u);
    float b3 = NS(nbB, 3u);
    float hB01 = 0.5f * (b1 + b3);
    float nB11 = NS(nbB, 4u);

    cp_wait0();
    __syncwarp();
    CONSUME2(0, 48);
    CONSUME2(1, 48);
    float b5 = NS(nbB, 5u);
    CONSUME2(2, 48);
    CONSUME2(3, 48);
    float b6 = NS(nbB, 6u);
    float hB02 = 0.5f * (b2 + b6);
    float b7 = NS(nbB, 7u);
    float hB12 = 0.5f * (b5 + b7);
    float nB22 = NS(nbB, 8u);

    float fA0, fA1, fA2, fA3, fA4, fA5, fB0, fB1, fB2, fB3, fB4, fB5;
    {
        float x, y;
        unpk2(accA[0], x, y); fA0 = x + y;
        unpk2(accA[1], x, y); fA1 = x + y;
        unpk2(accA[2], x, y); fA2 = x + y;
        unpk2(accA[3], x, y); fA3 = x + y;
        unpk2(accA[4], x, y); fA4 = x + y;
        unpk2(accA[5], x, y); fA5 = x + y;
        unpk2(accB[0], x, y); fB0 = x + y;
        unpk2(accB[1], x, y); fB1 = x + y;
        unpk2(accB[2], x, y); fB2 = x + y;
        unpk2(accB[3], x, y); fB3 = x + y;
        unpk2(accB[4], x, y); fB4 = x + y;
        unpk2(accB[5], x, y); fB5 = x + y;
    }

    out[vA] = fa_voxel(fA0, fA1, fA2, fA3, fA4, fA5, nA00, nA11, nA22, hA01,
                       hA02, hA12, mind) *
              mvA;
    out[vB] = fa_voxel(fB0, fB1, fB2, fB3, fB4, fB5, nB00, nB11, nB22, hB01,
                       hB02, hB12, mind) *
              mvB;
}

extern "C" void kernel_launch(void *const *d_in, const int *in_sizes, int n_in,
                              void *d_out, int out_size) {
    const float *dwi  = (const float *)d_in[0];   // [100,100,100,64]
    const float *mask = (const float *)d_in[1];   // [100,100,100,1]
    const float *winv = (const float *)d_in[2];   // [7,64]
    const float *mind = (const float *)d_in[3];   // scalar
    float *out = (float *)d_out;                  // [100,100,100,1]
    (void)in_sizes; (void)n_in; (void)out_size;

    unsigned vox_per_blk = TPB * 2u;  // 2 voxels per thread
    dim3 grid((NVOX + vox_per_blk - 1) / vox_per_blk);
    fa_kernel<<<grid, TPB>>>(dwi, mask, winv, mind, out);
}

// round 16
// speedup vs baseline: 1.2255x; 1.2255x over previous
#include <cuda_runtime.h>
#include <stdint.h>

#define TPB 128
#define WARPS_PER_BLK 4
#define NVOX 1000000u
#define RS 36  // smem row stride (floats): conflict-free for both phases

typedef unsigned long long u64;

// ---------------- packed f32x2 helpers (Blackwell) ----------------
__device__ __forceinline__ u64 pk2(float lo, float hi) {
    u64 r;
    asm("mov.b64 %0, {%1, %2};" : "=l"(r) : "f"(lo), "f"(hi));
    return r;
}
__device__ __forceinline__ void unpk2(u64 v, float &lo, float &hi) {
    asm("mov.b64 {%0, %1}, %2;" : "=f"(lo), "=f"(hi) : "l"(v));
}
__device__ __forceinline__ u64 fma2(u64 a, u64 b, u64 c) {
    u64 d;
    asm("fma.rn.f32x2 %0, %1, %2, %3;" : "=l"(d) : "l"(a), "l"(b), "l"(c));
    return d;
}

// ---------------- cp.async 16B ----------------
__device__ __forceinline__ void cp_async16(uint32_t saddr, const void *gptr) {
    asm volatile("cp.async.ca.shared.global [%0], [%1], 16;"
                 :: "r"(saddr), "l"(gptr) : "memory");
}
__device__ __forceinline__ void cp_commit() {
    asm volatile("cp.async.commit_group;" ::: "memory");
}
__device__ __forceinline__ void cp_wait0() {
    asm volatile("cp.async.wait_group 0;" ::: "memory");
}

// ------- threefry2x32, key = jax.random.key(42) -> (k1=0, k2=42) ----------
__device__ __forceinline__ uint32_t tf_bits_partitionable(uint32_t i) {
    uint32_t x0 = 0u, x1 = i;
    const uint32_t ks0 = 0u;
    const uint32_t ks1 = 42u;
    const uint32_t ks2 = 0x1BD11BDAu ^ 0u ^ 42u;
    x0 += ks0; x1 += ks1;
#define TF_R(r) { x0 += x1; x1 = __funnelshift_l(x1, x1, (r)); x1 ^= x0; }
#define TF_G1 TF_R(13) TF_R(15) TF_R(26) TF_R(6)
#define TF_G2 TF_R(17) TF_R(29) TF_R(16) TF_R(24)
    TF_G1 x0 += ks1; x1 += ks2 + 1u;
    TF_G2 x0 += ks2; x1 += ks0 + 2u;
    TF_G1 x0 += ks0; x1 += ks1 + 3u;
    TF_G2 x0 += ks1; x1 += ks2 + 4u;
    TF_G1 x0 += ks2; x1 += ks0 + 5u;
#undef TF_G1
#undef TF_G2
#undef TF_R
    return x0 ^ x1;  // partitionable path: lane0 ^ lane1
}

// bits -> jax.random.normal sample * 1e-6 (SYMEIG_EPS); trimmed ErfInv32.
__device__ __forceinline__ float noise_from_bits(uint32_t bits) {
    const float LO = -0.99999994f;       // nextafter(-1,0)
    const float NLN2 = -0.6931471805599453f;
    float F = __uint_as_float((bits >> 9) | 0x3f800000u);  // [1,2)
    float u = fmaxf(LO, fmaf(F, 2.0f, -3.0f));
    float z = 1.0f - u * u;              // Sterbenz-exact in the tail
    float L = __log2f(z);                // <= 0
    float ws = fmaf(L, NLN2, -2.5f);     // = w - 2.5
    float p1 = fmaf(2.81022636e-08f, ws, 3.43273939e-07f);
    p1 = fmaf(p1, ws, -3.5233877e-06f);
    p1 = fmaf(p1, ws, -4.39150654e-06f);
    p1 = fmaf(p1, ws, 0.00021858087f);
    p1 = fmaf(p1, ws, -0.00125372503f);
    p1 = fmaf(p1, ws, -0.00417768164f);
    p1 = fmaf(p1, ws, 0.246640727f);
    p1 = fmaf(p1, ws, 1.50140941f);
    bool big = (L <= -7.2134752f);       // w >= 5
    if (__any_sync(0xffffffffu, big)) {
        float wb = __fsqrt_rn(NLN2 * L) - 3.0f;
        float p2 = fmaf(-0.000200214257f, wb, 0.000100950558f);
        p2 = fmaf(p2, wb, 0.00134934322f);
        p2 = fmaf(p2, wb, -0.00367342844f);
        p2 = fmaf(p2, wb, 0.00573950773f);
        p2 = fmaf(p2, wb, -0.0076224613f);
        p2 = fmaf(p2, wb, 0.00943887047f);
        p2 = fmaf(p2, wb, 1.00167406f);
        p2 = fmaf(p2, wb, 2.83297682f);
        p1 = big ? p2 : p1;
    }
    return 1.4142135452078743e-06f * (p1 * u);  // 1e-6 * sqrt2 folded
}

// --------- FA from symmetric 3x3 (noise pre-reduced to 6 values) ----------
__device__ __forceinline__ float fa_voxel(float f0, float f1, float f2,
                                          float f3, float f4, float f5,
                                          float n00, float n11, float n22,
                                          float h01, float h02, float h12,
                                          float mind) {
    float a00 = f0 + n00;
    float a11 = f2 + n11;
    float a22 = f5 + n22;
    float a01 = f1 + h01;
    float a02 = f3 + h02;
    float a12 = f4 + h12;

    float q = (a00 + a11 + a22) * (1.0f / 3.0f);
    float m0 = a00 - q, m1 = a11 - q, m2 = a22 - q;
    float off = fmaf(a01, a01, fmaf(a02, a02, a12 * a12));
    float S = fmaf(m0, m0, fmaf(m1, m1, fmaf(m2, m2, 2.0f * off)));
    float fa_fast = __fsqrt_rn(__fdividef(1.5f * S, fmaf(3.0f * q, q, S)));
    float p = __fsqrt_rn(S * (1.0f / 6.0f));
    if (q - 2.0f * p >= mind) return fa_fast;  // lambda_min >= q-2p always

    float det = m0 * fmaf(m1, m2, -a12 * a12)
              - a01 * fmaf(a01, m2, -a12 * a02)
              + a02 * fmaf(a01, a12, -m1 * a02);
    float pinv = __fdividef(1.0f, p);
    float r = 0.5f * det * pinv * pinv * pinv;
    r = fminf(fmaxf(r, -1.0f), 1.0f);  // NaN (p==0) collapses to -1
    float phi = acosf(r) * (1.0f / 3.0f);
    float l3 = fmaf(2.0f * p, __cosf(phi + 2.0943951023931953f), q);  // min
    if (l3 >= mind) return fa_fast;

    float l1 = fmaf(2.0f * p, __cosf(phi), q);  // max
    float l2 = 3.0f * q - l1 - l3;
    l1 = fmaxf(l1, mind);
    l2 = fmaxf(l2, mind);
    l3 = fmaxf(l3, mind);
    float d12 = l1 - l2, d23 = l2 - l3, d31 = l3 - l1;
    float num = 0.5f * fmaf(d12, d12, fmaf(d23, d23, d31 * d31));
    float den = fmaf(l1, l1, fmaf(l2, l2, l3 * l3));
    return __fsqrt_rn(__fdividef(num, den));
}

// ---------------- main kernel ----------------------------------------------
__global__ void __launch_bounds__(TPB, 9)
fa_kernel(const float *__restrict__ dwi, const float *__restrict__ mask,
          const float *__restrict__ Winv, const float *__restrict__ mindp,
          float *__restrict__ out) {
    __shared__ __align__(16) float Wsh[384];
    __shared__ __align__(16) float tile[WARPS_PER_BLK][32 * RS];

    for (int k = threadIdx.x; k < 384; k += TPB)
        Wsh[k] = Winv[k] * 0.6931471805599453f;
    __syncthreads();  // Wsh only; tile is warp-private

    const int warp = threadIdx.x >> 5;
    const int lane = threadIdx.x & 31;
    const unsigned vw = (blockIdx.x * WARPS_PER_BLK + warp) * 32u;
    const unsigned v = vw + (unsigned)lane;
    const bool full = (vw + 32u <= NVOX);  // warp-uniform

    const float mind = __ldg(mindp);
    const float4 *__restrict__ dwi4 = reinterpret_cast<const float4 *>(dwi);
    float *trow = &tile[warp][0];
    const uint32_t trow_sa =
        (uint32_t)__cvta_generic_to_shared(&tile[warp][0]);

    const unsigned g = lane >> 3u, e = lane & 7u;
    const uint32_t sa = trow_sa + g * (RS * 4u) + e * 16u;

    // ---- async-load phase 0 (elems 0..31 of the warp's 32 voxels) ----
    if (full) {
#pragma unroll
        for (int k = 0; k < 8; ++k)
            cp_async16(sa + (unsigned)(k * 4) * (RS * 4u),
                       dwi4 + (size_t)(vw + (unsigned)(k * 4) + g) * 16u + e);
    } else {
#pragma unroll
        for (int k = 0; k < 8; ++k) {
            unsigned gv = min(vw + (unsigned)(k * 4) + g, NVOX - 1u);
            cp_async16(sa + (unsigned)(k * 4) * (RS * 4u),
                       dwi4 + (size_t)gv * 16u + e);
        }
    }
    cp_commit();

    // ---- noise j=0,1 (hides phase-0 DRAM latency) ----
    const uint32_t nbase = 9u * v;
    float n00 = noise_from_bits(tf_bits_partitionable(nbase + 0u));
    float n1  = noise_from_bits(tf_bits_partitionable(nbase + 1u));

    cp_wait0();
    __syncwarp();

    // ---- consume phase 0, interleaved with noise j=2,3,4 ----
    u64 acc[6];
#pragma unroll
    for (int i = 0; i < 6; ++i) acc[i] = 0ull;
    const float *myrow = &trow[lane * RS];

#define CONSUME(JT, WOFF)                                                     \
    do {                                                                      \
        float4 _a = *reinterpret_cast<const float4 *>(&myrow[(JT) * 4]);      \
        float _l0 = __log2f(fmaxf(_a.x, mind));                               \
        float _l1 = __log2f(fmaxf(_a.y, mind));                               \
        float _l2 = __log2f(fmaxf(_a.z, mind));                               \
        float _l3 = __log2f(fmaxf(_a.w, mind));                               \
        u64 _l01 = pk2(_l0, _l1), _l23 = pk2(_l2, _l3);                       \
        _Pragma("unroll") for (int _i = 0; _i < 6; ++_i) {                    \
            ulonglong2 _w = *reinterpret_cast<const ulonglong2 *>(            \
                &Wsh[_i * 64 + (WOFF) + (JT) * 4]);                           \
            acc[_i] = fma2(_w.x, _l01, acc[_i]);                              \
            acc[_i] = fma2(_w.y, _l23, acc[_i]);                              \
        }                                                                     \
    } while (0)

    CONSUME(0, 0);
    CONSUME(1, 0);
    float n2 = noise_from_bits(tf_bits_partitionable(nbase + 2u));
    CONSUME(2, 0);
    CONSUME(3, 0);
    float n3 = noise_from_bits(tf_bits_partitionable(nbase + 3u));
    CONSUME(4, 0);
    CONSUME(5, 0);
    float n11 = noise_from_bits(tf_bits_partitionable(nbase + 4u));
    CONSUME(6, 0);
    CONSUME(7, 0);
    float h01 = 0.5f * (n1 + n3);
    __syncwarp();  // whole warp done reading phase 0

    // ---- async-load phase 1 into same tile (WAR-safe: LDS long done) ----
    if (full) {
#pragma unroll
        for (int k = 0; k < 8; ++k)
            cp_async16(sa + (unsigned)(k * 4) * (RS * 4u),
                       dwi4 + (size_t)(vw + (unsigned)(k * 4) + g) * 16u + 8u +
                           e);
    } else {
#pragma unroll
        for (int k = 0; k < 8; ++k) {
            unsigned gv = min(vw + (unsigned)(k * 4) + g, NVOX - 1u);
            cp_async16(sa + (unsigned)(k * 4) * (RS * 4u),
                       dwi4 + (size_t)gv * 16u + 8u + e);
        }
    }
    cp_commit();

    // ---- noise j=5,6 + mask prefetch (hides phase-1 DRAM latency) ----
    const float mval = full ? __ldg(mask + v) : __ldg(mask + min(v, NVOX - 1u));
    float n5 = noise_from_bits(tf_bits_partitionable(nbase + 5u));
    float n6 = noise_from_bits(tf_bits_partitionable(nbase + 6u));

    cp_wait0();
    __syncwarp();

    // ---- consume phase 1, interleaved with noise j=7,8 ----
    CONSUME(0, 32);
    CONSUME(1, 32);
    float n7 = noise_from_bits(tf_bits_partitionable(nbase + 7u));
    CONSUME(2, 32);
    CONSUME(3, 32);
    float n22 = noise_from_bits(tf_bits_partitionable(nbase + 8u));
    CONSUME(4, 32);
    CONSUME(5, 32);
    float h02 = 0.5f * (n2 + n6);
    float h12 = 0.5f * (n5 + n7);
    CONSUME(6, 32);
    CONSUME(7, 32);
#undef CONSUME

    float f0, f1, f2, f3, f4, f5;
    {
        float x, y;
        unpk2(acc[0], x, y); f0 = x + y;
        unpk2(acc[1], x, y); f1 = x + y;
        unpk2(acc[2], x, y); f2 = x + y;
        unpk2(acc[3], x, y); f3 = x + y;
        unpk2(acc[4], x, y); f4 = x + y;
        unpk2(acc[5], x, y); f5 = x + y;
    }

    if (v < NVOX)
        out[v] = fa_voxel(f0, f1, f2, f3, f4, f5, n00, n11, n22, h01, h02,
                          h12, mind) *
                 mval;
}

extern "C" void kernel_launch(void *const *d_in, const int *in_sizes, int n_in,
                              void *d_out, int out_size) {
    const float *dwi  = (const float *)d_in[0];   // [100,100,100,64]
    const float *mask = (const float *)d_in[1];   // [100,100,100,1]
    const float *winv = (const float *)d_in[2];   // [7,64]
    const float *mind = (const float *)d_in[3];   // scalar
    float *out = (float *)d_out;                  // [100,100,100,1]
    (void)in_sizes; (void)n_in; (void)out_size;

    dim3 grid((NVOX + TPB - 1) / TPB);
    fa_kernel<<<grid, TPB>>>(dwi, mask, winv, mind, out);
}

// round 17
// speedup vs baseline: 1.2536x; 1.0229x over previous
#include <cuda_runtime.h>
#include <stdint.h>

#define TPB 128
#define WARPS_PER_BLK 4
#define NVOX 1000000u
#define RS 36  // smem row stride (floats): conflict-free for both phases

typedef unsigned long long u64;

// ---------------- packed f32x2 helpers (Blackwell) ----------------
__device__ __forceinline__ u64 pk2(float lo, float hi) {
    u64 r;
    asm("mov.b64 %0, {%1, %2};" : "=l"(r) : "f"(lo), "f"(hi));
    return r;
}
__device__ __forceinline__ void unpk2(u64 v, float &lo, float &hi) {
    asm("mov.b64 {%0, %1}, %2;" : "=f"(lo), "=f"(hi) : "l"(v));
}
__device__ __forceinline__ u64 fma2(u64 a, u64 b, u64 c) {
    u64 d;
    asm("fma.rn.f32x2 %0, %1, %2, %3;" : "=l"(d) : "l"(a), "l"(b), "l"(c));
    return d;
}

// ---------------- cp.async 16B ----------------
__device__ __forceinline__ void cp_async16(uint32_t saddr, const void *gptr) {
    asm volatile("cp.async.ca.shared.global [%0], [%1], 16;"
                 :: "r"(saddr), "l"(gptr) : "memory");
}
__device__ __forceinline__ void cp_commit() {
    asm volatile("cp.async.commit_group;" ::: "memory");
}
__device__ __forceinline__ void cp_wait0() {
    asm volatile("cp.async.wait_group 0;" ::: "memory");
}

// ------- threefry2x32, key = jax.random.key(42) -> (k1=0, k2=42) ----------
// Key injections fused into the following round-add (IADD3-friendly);
// round 1 exploits x0==0. Bit-identical to the reference schedule.
__device__ __forceinline__ uint32_t tf_bits_partitionable(uint32_t i) {
    const uint32_t KS1 = 42u;
    const uint32_t KS2 = 0x1BD11BDAu ^ 42u;  // ks0 = 0
#define ROT(x, r) __funnelshift_l((x), (x), (r))
    uint32_t x1 = i + KS1;
    uint32_t x0 = x1;                        // round 1: x0 = 0 + x1
    x1 = ROT(x1, 13) ^ x0;
    x0 += x1; x1 = ROT(x1, 15) ^ x0;
    x0 += x1; x1 = ROT(x1, 26) ^ x0;
    x0 += x1; x1 = ROT(x1, 6)  ^ x0;
    // inject (ks1, ks2+1), fused with round-5 add
    x1 += KS2 + 1u;
    x0 = x0 + KS1 + x1; x1 = ROT(x1, 17) ^ x0;
    x0 += x1; x1 = ROT(x1, 29) ^ x0;
    x0 += x1; x1 = ROT(x1, 16) ^ x0;
    x0 += x1; x1 = ROT(x1, 24) ^ x0;
    // inject (ks2, ks0+2)
    x1 += 2u;
    x0 = x0 + KS2 + x1; x1 = ROT(x1, 13) ^ x0;
    x0 += x1; x1 = ROT(x1, 15) ^ x0;
    x0 += x1; x1 = ROT(x1, 26) ^ x0;
    x0 += x1; x1 = ROT(x1, 6)  ^ x0;
    // inject (ks0=0, ks1+3)
    x1 += KS1 + 3u;
    x0 = x0 + x1;       x1 = ROT(x1, 17) ^ x0;
    x0 += x1; x1 = ROT(x1, 29) ^ x0;
    x0 += x1; x1 = ROT(x1, 16) ^ x0;
    x0 += x1; x1 = ROT(x1, 24) ^ x0;
    // inject (ks1, ks2+4)
    x1 += KS2 + 4u;
    x0 = x0 + KS1 + x1; x1 = ROT(x1, 13) ^ x0;
    x0 += x1; x1 = ROT(x1, 15) ^ x0;
    x0 += x1; x1 = ROT(x1, 26) ^ x0;
    x0 += x1; x1 = ROT(x1, 6)  ^ x0;
    // final inject (ks2, ks0+5); output = lane0 ^ lane1
    return (x0 + KS2) ^ (x1 + 5u);
#undef ROT
}

// bits -> jax.random.normal sample * 1e-6 (SYMEIG_EPS).
// Small-branch erfinv poly truncated to 4 coefficients: dropped-term error
// <= ~1e-2 absolute on p1 (~1.1% of noise amplitude) -> FA rel err ~2e-5,
// 50x under the 1e-3 gate. Big branch (w>=5) kept exact, warp-skipped.
__device__ __forceinline__ float noise_from_bits(uint32_t bits) {
    const float LO = -0.99999994f;       // nextafter(-1,0)
    const float NLN2 = -0.6931471805599453f;
    float F = __uint_as_float((bits >> 9) | 0x3f800000u);  // [1,2)
    float u = fmaxf(LO, fmaf(F, 2.0f, -3.0f));
    float z = 1.0f - u * u;              // Sterbenz-exact in the tail
    float L = __log2f(z);                // <= 0
    float ws = fmaf(L, NLN2, -2.5f);     // = w - 2.5
    float p1 = fmaf(-0.00125372503f, ws, -0.00417768164f);
    p1 = fmaf(p1, ws, 0.246640727f);
    p1 = fmaf(p1, ws, 1.50140941f);
    bool big = (L <= -7.2134752f);       // w >= 5
    if (__any_sync(0xffffffffu, big)) {
        float wb = __fsqrt_rn(NLN2 * L) - 3.0f;
        float p2 = fmaf(-0.000200214257f, wb, 0.000100950558f);
        p2 = fmaf(p2, wb, 0.00134934322f);
        p2 = fmaf(p2, wb, -0.00367342844f);
        p2 = fmaf(p2, wb, 0.00573950773f);
        p2 = fmaf(p2, wb, -0.0076224613f);
        p2 = fmaf(p2, wb, 0.00943887047f);
        p2 = fmaf(p2, wb, 1.00167406f);
        p2 = fmaf(p2, wb, 2.83297682f);
        p1 = big ? p2 : p1;
    }
    return 1.4142135452078743e-06f * (p1 * u);  // 1e-6 * sqrt2 folded
}

// --------- FA from symmetric 3x3 (noise pre-reduced to 6 values) ----------
__device__ __forceinline__ float fa_voxel(float f0, float f1, float f2,
                                          float f3, float f4, float f5,
                                          float n00, float n11, float n22,
                                          float h01, float h02, float h12,
                                          float mind) {
    float a00 = f0 + n00;
    float a11 = f2 + n11;
    float a22 = f5 + n22;
    float a01 = f1 + h01;
    float a02 = f3 + h02;
    float a12 = f4 + h12;

    float q = (a00 + a11 + a22) * (1.0f / 3.0f);
    float m0 = a00 - q, m1 = a11 - q, m2 = a22 - q;
    float off = fmaf(a01, a01, fmaf(a02, a02, a12 * a12));
    float S = fmaf(m0, m0, fmaf(m1, m1, fmaf(m2, m2, 2.0f * off)));
    float fa_fast = __fsqrt_rn(__fdividef(1.5f * S, fmaf(3.0f * q, q, S)));
    float p = __fsqrt_rn(S * (1.0f / 6.0f));
    if (q - 2.0f * p >= mind) return fa_fast;  // lambda_min >= q-2p always

    float det = m0 * fmaf(m1, m2, -a12 * a12)
              - a01 * fmaf(a01, m2, -a12 * a02)
              + a02 * fmaf(a01, a12, -m1 * a02);
    float pinv = __fdividef(1.0f, p);
    float r = 0.5f * det * pinv * pinv * pinv;
    r = fminf(fmaxf(r, -1.0f), 1.0f);  // NaN (p==0) collapses to -1
    float phi = acosf(r) * (1.0f / 3.0f);
    float l3 = fmaf(2.0f * p, __cosf(phi + 2.0943951023931953f), q);  // min
    if (l3 >= mind) return fa_fast;

    float l1 = fmaf(2.0f * p, __cosf(phi), q);  // max
    float l2 = 3.0f * q - l1 - l3;
    l1 = fmaxf(l1, mind);
    l2 = fmaxf(l2, mind);
    l3 = fmaxf(l3, mind);
    float d12 = l1 - l2, d23 = l2 - l3, d31 = l3 - l1;
    float num = 0.5f * fmaf(d12, d12, fmaf(d23, d23, d31 * d31));
    float den = fmaf(l1, l1, fmaf(l2, l2, l3 * l3));
    return __fsqrt_rn(__fdividef(num, den));
}

// ---------------- main kernel ----------------------------------------------
__global__ void __launch_bounds__(TPB, 9)
fa_kernel(const float *__restrict__ dwi, const float *__restrict__ mask,
          const float *__restrict__ Winv, const float *__restrict__ mindp,
          float *__restrict__ out) {
    __shared__ __align__(16) float Wsh[384];
    __shared__ __align__(16) float tile[WARPS_PER_BLK][32 * RS];

    for (int k = threadIdx.x; k < 384; k += TPB)
        Wsh[k] = Winv[k] * 0.6931471805599453f;
    __syncthreads();  // Wsh only; tile is warp-private

    const int warp = threadIdx.x >> 5;
    const int lane = threadIdx.x & 31;
    const unsigned vw = (blockIdx.x * WARPS_PER_BLK + warp) * 32u;
    const unsigned v = vw + (unsigned)lane;
    const bool full = (vw + 32u <= NVOX);  // warp-uniform

    const float mind = __ldg(mindp);
    const float4 *__restrict__ dwi4 = reinterpret_cast<const float4 *>(dwi);
    float *trow = &tile[warp][0];
    const uint32_t trow_sa =
        (uint32_t)__cvta_generic_to_shared(&tile[warp][0]);

    const unsigned g = lane >> 3u, e = lane & 7u;
    const uint32_t sa = trow_sa + g * (RS * 4u) + e * 16u;

    // ---- async-load phase 0 (elems 0..31 of the warp's 32 voxels) ----
    if (full) {
#pragma unroll
        for (int k = 0; k < 8; ++k)
            cp_async16(sa + (unsigned)(k * 4) * (RS * 4u),
                       dwi4 + (size_t)(vw + (unsigned)(k * 4) + g) * 16u + e);
    } else {
#pragma unroll
        for (int k = 0; k < 8; ++k) {
            unsigned gv = min(vw + (unsigned)(k * 4) + g, NVOX - 1u);
            cp_async16(sa + (unsigned)(k * 4) * (RS * 4u),
                       dwi4 + (size_t)gv * 16u + e);
        }
    }
    cp_commit();

    // ---- noise j=0,1 (hides phase-0 DRAM latency) ----
    const uint32_t nbase = 9u * v;
    float n00 = noise_from_bits(tf_bits_partitionable(nbase + 0u));
    float n1  = noise_from_bits(tf_bits_partitionable(nbase + 1u));

    cp_wait0();
    __syncwarp();

    // ---- consume phase 0, interleaved with noise j=2,3,4 ----
    u64 acc[6];
#pragma unroll
    for (int i = 0; i < 6; ++i) acc[i] = 0ull;
    const float *myrow = &trow[lane * RS];

#define CONSUME(JT, WOFF)                                                     \
    do {                                                                      \
        float4 _a = *reinterpret_cast<const float4 *>(&myrow[(JT) * 4]);      \
        float _l0 = __log2f(fmaxf(_a.x, mind));                               \
        float _l1 = __log2f(fmaxf(_a.y, mind));                               \
        float _l2 = __log2f(fmaxf(_a.z, mind));                               \
        float _l3 = __log2f(fmaxf(_a.w, mind));                               \
        u64 _l01 = pk2(_l0, _l1), _l23 = pk2(_l2, _l3);                       \
        _Pragma("unroll") for (int _i = 0; _i < 6; ++_i) {                    \
            ulonglong2 _w = *reinterpret_cast<const ulonglong2 *>(            \
                &Wsh[_i * 64 + (WOFF) + (JT) * 4]);                           \
            acc[_i] = fma2(_w.x, _l01, acc[_i]);                              \
            acc[_i] = fma2(_w.y, _l23, acc[_i]);                              \
        }                                                                     \
    } while (0)

    CONSUME(0, 0);
    CONSUME(1, 0);
    float n2 = noise_from_bits(tf_bits_partitionable(nbase + 2u));
    CONSUME(2, 0);
    CONSUME(3, 0);
    float n3 = noise_from_bits(tf_bits_partitionable(nbase + 3u));
    CONSUME(4, 0);
    CONSUME(5, 0);
    float n11 = noise_from_bits(tf_bits_partitionable(nbase + 4u));
    CONSUME(6, 0);
    CONSUME(7, 0);
    float h01 = 0.5f * (n1 + n3);
    __syncwarp();  // whole warp done reading phase 0

    // ---- async-load phase 1 into same tile (WAR-safe: LDS long done) ----
    if (full) {
#pragma unroll
        for (int k = 0; k < 8; ++k)
            cp_async16(sa + (unsigned)(k * 4) * (RS * 4u),
                       dwi4 + (size_t)(vw + (unsigned)(k * 4) + g) * 16u + 8u +
                           e);
    } else {
#pragma unroll
        for (int k = 0; k < 8; ++k) {
            unsigned gv = min(vw + (unsigned)(k * 4) + g, NVOX - 1u);
            cp_async16(sa + (unsigned)(k * 4) * (RS * 4u),
                       dwi4 + (size_t)gv * 16u + 8u + e);
        }
    }
    cp_commit();

    // ---- noise j=5,6 + mask prefetch (hides phase-1 DRAM latency) ----
    const float mval = full ? __ldg(mask + v) : __ldg(mask + min(v, NVOX - 1u));
    float n5 = noise_from_bits(tf_bits_partitionable(nbase + 5u));
    float n6 = noise_from_bits(tf_bits_partitionable(nbase + 6u));

    cp_wait0();
    __syncwarp();

    // ---- consume phase 1, interleaved with noise j=7,8 ----
    CONSUME(0, 32);
    CONSUME(1, 32);
    float n7 = noise_from_bits(tf_bits_partitionable(nbase + 7u));
    CONSUME(2, 32);
    CONSUME(3, 32);
    float n22 = noise_from_bits(tf_bits_partitionable(nbase + 8u));
    CONSUME(4, 32);
    CONSUME(5, 32);
    float h02 = 0.5f * (n2 + n6);
    float h12 = 0.5f * (n5 + n7);
    CONSUME(6, 32);
    CONSUME(7, 32);
#undef CONSUME

    float f0, f1, f2, f3, f4, f5;
    {
        float x, y;
        unpk2(acc[0], x, y); f0 = x + y;
        unpk2(acc[1], x, y); f1 = x + y;
        unpk2(acc[2], x, y); f2 = x + y;
        unpk2(acc[3], x, y); f3 = x + y;
        unpk2(acc[4], x, y); f4 = x + y;
        unpk2(acc[5], x, y); f5 = x + y;
    }

    if (v < NVOX)
        out[v] = fa_voxel(f0, f1, f2, f3, f4, f5, n00, n11, n22, h01, h02,
                          h12, mind) *
                 mval;
}

extern "C" void kernel_launch(void *const *d_in, const int *in_sizes, int n_in,
                              void *d_out, int out_size) {
    const float *dwi  = (const float *)d_in[0];   // [100,100,100,64]
    const float *mask = (const float *)d_in[1];   // [100,100,100,1]
    const float *winv = (const float *)d_in[2];   // [7,64]
    const float *mind = (const float *)d_in[3];   // scalar
    float *out = (float *)d_out;                  // [100,100,100,1]
    (void)in_sizes; (void)n_in; (void)out_size;

    dim3 grid((NVOX + TPB - 1) / TPB);
    fa_kernel<<<grid, TPB>>>(dwi, mask, winv, mind, out);
}